// round 14
// baseline (speedup 1.0000x reference)
#include <cuda_runtime.h>
#include <cuda_fp16.h>

#define NN 100000
#define NE 1600000
#define DD 128
#define LN_EPS 1e-5f
#define CAP 64    // max degree capacity (Poisson(16): P(deg>=64) ~ 1e-18)
#define MB 128    // nodes per gemm block
#define LDA 136   // smem row stride in halves (128 + 8 pad -> conflict-free LDSM)
#define LDC 132   // smem fp32 row stride for epilogue (div by 4 -> 16B aligned)

// ---------------- scratch ----------------------------------------------------
__device__ int   g_cnt[NN];
__device__ float g_ideg[NN];
__device__ int   g_slot[NN * CAP];    // per-node dst buckets (25.6MB, L2-resident)
__device__ uint4 g_xs4[NN * 16];      // fp16 x (UNSCALED), [node][128] 8 halves/uint4
__device__ uint4 g_nh4[NN * 16];      // fp16 neigh, same layout
__device__ uint4 g_Wh4[DD * DD / 8];  // fp16 W, row-major [j][k] (== B col-major)

// ---------------- scat + conv fused (grid-split; conv independent of scat) ---
#define SCAT_BLKS ((NE / 8 + 255) / 256)
__global__ void k_scatconv(const int4* __restrict__ src4,
                           const int4* __restrict__ dst4,
                           const float4* __restrict__ x4,
                           const float4* __restrict__ W4) {
    if (blockIdx.x < SCAT_BLKS) {
        int i = blockIdx.x * blockDim.x + threadIdx.x;
        if (i < NE / 8) {
            int4 sa = src4[2 * i], sb = src4[2 * i + 1];
            int4 da = dst4[2 * i], db = dst4[2 * i + 1];
            int p0 = atomicAdd(&g_cnt[sa.x], 1);
            int p1 = atomicAdd(&g_cnt[sa.y], 1);
            int p2 = atomicAdd(&g_cnt[sa.z], 1);
            int p3 = atomicAdd(&g_cnt[sa.w], 1);
            int p4 = atomicAdd(&g_cnt[sb.x], 1);
            int p5 = atomicAdd(&g_cnt[sb.y], 1);
            int p6 = atomicAdd(&g_cnt[sb.z], 1);
            int p7 = atomicAdd(&g_cnt[sb.w], 1);
            g_slot[sa.x * CAP + p0] = da.x;
            g_slot[sa.y * CAP + p1] = da.y;
            g_slot[sa.z * CAP + p2] = da.z;
            g_slot[sa.w * CAP + p3] = da.w;
            g_slot[sb.x * CAP + p4] = db.x;
            g_slot[sb.y * CAP + p5] = db.y;
            g_slot[sb.z * CAP + p6] = db.z;
            g_slot[sb.w * CAP + p7] = db.w;
        }
    } else {
        int i = (blockIdx.x - SCAT_BLKS) * blockDim.x + threadIdx.x;
        if (i < NN * 16) {
            float4 v0 = x4[i * 2];
            float4 v1 = x4[i * 2 + 1];
            __half2 h0 = __floats2half2_rn(v0.x, v0.y);
            __half2 h1 = __floats2half2_rn(v0.z, v0.w);
            __half2 h2 = __floats2half2_rn(v1.x, v1.y);
            __half2 h3 = __floats2half2_rn(v1.z, v1.w);
            uint4 u;
            u.x = *(unsigned*)&h0; u.y = *(unsigned*)&h1;
            u.z = *(unsigned*)&h2; u.w = *(unsigned*)&h3;
            g_xs4[i] = u;
        } else if (i < NN * 16 + DD * DD / 8) {
            int j = i - NN * 16;
            float4 v0 = W4[j * 2];
            float4 v1 = W4[j * 2 + 1];
            __half2 h0 = __floats2half2_rn(v0.x, v0.y);
            __half2 h1 = __floats2half2_rn(v0.z, v0.w);
            __half2 h2 = __floats2half2_rn(v1.x, v1.y);
            __half2 h3 = __floats2half2_rn(v1.z, v1.w);
            uint4 u;
            u.x = *(unsigned*)&h0; u.y = *(unsigned*)&h1;
            u.z = *(unsigned*)&h2; u.w = *(unsigned*)&h3;
            g_Wh4[j] = u;
        }
    }
}

// ---------------- prep: invdeg (after scat) ----------------------------------
__global__ void k_prep() {
    int i = blockIdx.x * blockDim.x + threadIdx.x;
    if (i < NN) {
        int d = g_cnt[i];
        g_ideg[i] = 1.0f / (float)(d > 1 ? d : 1);
    }
}

// ---------------- gather: warp/node, 16 lanes/edge, fp32 FFMA, 4-edge unroll -
__device__ __forceinline__ void facc(float* a, uint4 p, float w) {
    __half2* hp = (__half2*)&p;
    #pragma unroll
    for (int i = 0; i < 4; i++) {
        float2 f = __half22float2(hp[i]);
        a[2 * i]     = fmaf(f.x, w, a[2 * i]);
        a[2 * i + 1] = fmaf(f.y, w, a[2 * i + 1]);
    }
}

__global__ void k_gather() {
    int gw = (blockIdx.x * blockDim.x + threadIdx.x) >> 5;
    int lane = threadIdx.x & 31;
    if (gw >= NN) return;
    int n = g_cnt[gw];
    const int* slots = &g_slot[gw * CAP];
    int hw = lane >> 4, l16 = lane & 15;
    float a[8] = {0.f, 0.f, 0.f, 0.f, 0.f, 0.f, 0.f, 0.f};
    int e = 0;
    for (; e + 4 <= n; e += 4) {
        int d0 = slots[e + hw];
        int d1 = slots[e + 2 + hw];
        float w0 = g_ideg[d0], w1 = g_ideg[d1];
        uint4 p0 = g_xs4[d0 * 16 + l16];
        uint4 p1 = g_xs4[d1 * 16 + l16];
        facc(a, p0, w0);
        facc(a, p1, w1);
    }
    for (; e < n; e += 2) {
        if (e + hw < n) {
            int d0 = slots[e + hw];
            facc(a, g_xs4[d0 * 16 + l16], g_ideg[d0]);
        }
    }
    #pragma unroll
    for (int i = 0; i < 8; i++)
        a[i] += __shfl_xor_sync(0xffffffffu, a[i], 16);
    if (hw == 0) {
        __half2 h0 = __floats2half2_rn(a[0], a[1]);
        __half2 h1 = __floats2half2_rn(a[2], a[3]);
        __half2 h2 = __floats2half2_rn(a[4], a[5]);
        __half2 h3 = __floats2half2_rn(a[6], a[7]);
        uint4 u;
        u.x = *(unsigned*)&h0; u.y = *(unsigned*)&h1;
        u.z = *(unsigned*)&h2; u.w = *(unsigned*)&h3;
        g_nh4[gw * 16 + l16] = u;
    }
}

// ---------------- mma helpers ------------------------------------------------
__device__ __forceinline__ void ldsm_x4(unsigned* r, const __half* p) {
    unsigned addr = (unsigned)__cvta_generic_to_shared(p);
    asm volatile("ldmatrix.sync.aligned.m8n8.x4.shared.b16 {%0,%1,%2,%3}, [%4];"
                 : "=r"(r[0]), "=r"(r[1]), "=r"(r[2]), "=r"(r[3]) : "r"(addr));
}
__device__ __forceinline__ void mma16816(float* c, const unsigned* a,
                                         unsigned b0, unsigned b1) {
    asm volatile(
        "mma.sync.aligned.m16n8k16.row.col.f32.f16.f16.f32 "
        "{%0,%1,%2,%3}, {%4,%5,%6,%7}, {%8,%9}, {%0,%1,%2,%3};"
        : "+f"(c[0]), "+f"(c[1]), "+f"(c[2]), "+f"(c[3])
        : "r"(a[0]), "r"(a[1]), "r"(a[2]), "r"(a[3]), "r"(b0), "r"(b1));
}

// ---------------- HMMA GEMM + smem-staged epilogue (residual + LN) -----------
__global__ void __launch_bounds__(256, 3)
k_gemmln(const float4* __restrict__ xg,
         const float4* __restrict__ biasg,
         const float4* __restrict__ gammag,
         const float4* __restrict__ betag,
         float4* __restrict__ outg) {
    extern __shared__ char smembuf[];
    __half* sA  = (__half*)smembuf;             // phase A: [128][LDA]
    __half* sB  = (__half*)(smembuf + MB * LDA * 2);
    float*  sAcc = (float*)smembuf;             // phase B: [128][LDC] fp32
    int t = threadIdx.x, lane = t & 31, warp = t >> 5;
    int n0 = blockIdx.x * MB;

    // ---- phase A: stage + mainloop ----
    for (int i = t; i < MB * 16; i += 256) {
        int r = i >> 4, c = i & 15;
        uint4 v = (n0 + r < NN) ? g_nh4[(n0 + r) * 16 + c]
                                : make_uint4(0u, 0u, 0u, 0u);
        *(uint4*)&sA[r * LDA + c * 8] = v;
    }
    for (int i = t; i < DD * 16; i += 256) {
        int r = i >> 4, c = i & 15;
        *(uint4*)&sB[r * LDA + c * 8] = g_Wh4[r * 16 + c];
    }
    __syncthreads();

    int mr = warp * 16;
    int arow = mr + (lane & 15);
    int acol = (lane >> 4) * 8;

    float acc[16][4];
    #pragma unroll
    for (int i = 0; i < 16; i++)
        #pragma unroll
        for (int j = 0; j < 4; j++) acc[i][j] = 0.f;

    int brow_off = (lane & 7) + ((lane >> 4) << 3);
    int bcol = lane & 8;
    #pragma unroll
    for (int kc = 0; kc < 8; kc++) {
        unsigned af[4];
        ldsm_x4(af, &sA[arow * LDA + kc * 16 + acol]);
        #pragma unroll
        for (int p = 0; p < 8; p++) {
            int j0 = p * 16;
            unsigned bf[4];
            ldsm_x4(bf, &sB[(j0 + brow_off) * LDA + kc * 16 + bcol]);
            mma16816(acc[2 * p],     af, bf[0], bf[1]);
            mma16816(acc[2 * p + 1], af, bf[2], bf[3]);
        }
    }
    __syncthreads();   // all warps done reading sA/sB before overwrite

    // ---- dump acc -> smem fp32 [row][LDC] ----
    {
        int qrow = lane >> 2;
        int qcol = (lane & 3) * 2;
        int rlo = mr + qrow, rhi = rlo + 8;
        #pragma unroll
        for (int t16 = 0; t16 < 16; t16++) {
            int n = (t16 >> 1) * 16 + (t16 & 1) * 8 + qcol;
            *(float2*)&sAcc[rlo * LDC + n] = make_float2(acc[t16][0], acc[t16][1]);
            *(float2*)&sAcc[rhi * LDC + n] = make_float2(acc[t16][2], acc[t16][3]);
        }
    }
    __syncthreads();

    // ---- phase B: streaming epilogue, thread = (row, 64-col half) ----
    int row  = t >> 1;            // local row 0..127
    int half = t & 1;
    int grow = n0 + row;
    bool ok  = grow < NN;
    int c4   = half * 16;         // float4 col base
    float s = 0.f, ss = 0.f;
    #pragma unroll
    for (int i = 0; i < 16; i++) {
        float4 xv = ok ? xg[grow * 32 + c4 + i] : make_float4(0.f, 0.f, 0.f, 0.f);
        float4 av = *(float4*)&sAcc[row * LDC + (c4 + i) * 4];
        float4 bv = biasg[c4 + i];
        float h0 = xv.x + av.x + bv.x;
        float h1 = xv.y + av.y + bv.y;
        float h2 = xv.z + av.z + bv.z;
        float h3 = xv.w + av.w + bv.w;
        s  += h0 + h1 + h2 + h3;
        ss += h0 * h0 + h1 * h1 + h2 * h2 + h3 * h3;
        *(float4*)&sAcc[row * LDC + (c4 + i) * 4] = make_float4(h0, h1, h2, h3);
    }
    s  += __shfl_xor_sync(0xffffffffu, s,  1);
    ss += __shfl_xor_sync(0xffffffffu, ss, 1);
    float mean = s * (1.0f / 128.0f);
    float var  = ss * (1.0f / 128.0f) - mean * mean;
    float rstd = rsqrtf(var + LN_EPS);

    #pragma unroll
    for (int i = 0; i < 16; i++) {
        float4 hv = *(float4*)&sAcc[row * LDC + (c4 + i) * 4];
        float4 gv = gammag[c4 + i];
        float4 tv = betag[c4 + i];
        float4 o;
        o.x = (hv.x - mean) * rstd * gv.x + tv.x;
        o.y = (hv.y - mean) * rstd * gv.y + tv.y;
        o.z = (hv.z - mean) * rstd * gv.z + tv.z;
        o.w = (hv.w - mean) * rstd * gv.w + tv.w;
        if (ok) outg[grow * 32 + c4 + i] = o;
    }
}

// ---------------- launch -----------------------------------------------------
extern "C" void kernel_launch(void* const* d_in, const int* in_sizes, int n_in,
                              void* d_out, int out_size) {
    const float* x     = (const float*)d_in[0];
    const float* W     = (const float*)d_in[1];
    const float* bias  = (const float*)d_in[2];
    const float* gamma = (const float*)d_in[3];
    const float* beta  = (const float*)d_in[4];
    const int*   ei    = (const int*)d_in[5];
    const int4*  src4  = (const int4*)ei;
    const int4*  dst4  = (const int4*)(ei + NE);

    const int smemA = (MB + DD) * LDA * (int)sizeof(__half);   // 69632B
    const int smemB = MB * LDC * (int)sizeof(float);           // 67584B
    const int smem  = smemA > smemB ? smemA : smemB;
    cudaFuncSetAttribute(k_gemmln, cudaFuncAttributeMaxDynamicSharedMemorySize, smem);

    void* cnt_ptr = nullptr;
    cudaGetSymbolAddress(&cnt_ptr, g_cnt);
    cudaMemsetAsync(cnt_ptr, 0, NN * sizeof(int));

    const int conv_blks = (NN * 16 + DD * DD / 8 + 255) / 256;
    k_scatconv<<<SCAT_BLKS + conv_blks, 256>>>(src4, dst4,
                                               (const float4*)x,
                                               (const float4*)W);
    k_prep<<<(NN + 255) / 256, 256>>>();
    k_gather<<<(NN * 32 + 255) / 256, 256>>>();
    k_gemmln<<<(NN + MB - 1) / MB, 256, smem>>>(
        (const float4*)x, (const float4*)bias, (const float4*)gamma,
        (const float4*)beta, (float4*)d_out);
}

// round 17
// speedup vs baseline: 1.2522x; 1.2522x over previous
#include <cuda_runtime.h>
#include <cuda_fp16.h>

#define NN 100000
#define NE 1600000
#define DD 128
#define LN_EPS 1e-5f
#define CAP 64    // max degree capacity (Poisson(16): P(deg>=64) ~ 1e-18)
#define MB 64     // rows per gemm block (8 warps = 4 row-groups x 2 col-groups)
#define LDA 136   // smem row stride in halves (128 + 8 pad -> conflict-free LDSM)

// ---------------- scratch ----------------------------------------------------
__device__ int   g_cnt[NN];
__device__ float g_ideg[NN];
__device__ int   g_slot[NN * CAP];    // per-node dst buckets (25.6MB, L2-resident)
__device__ uint4 g_xs4[NN * 16];      // fp16 x (UNSCALED), [node][128] 8 halves/uint4
__device__ uint4 g_nh4[NN * 16];      // fp16 neigh, same layout
__device__ uint4 g_Wh4[DD * DD / 8];  // fp16 W, row-major [j][k] (== B col-major)

// ---------------- scat + conv fused (grid-split; conv independent of scat) ---
#define SCAT_BLKS ((NE / 8 + 255) / 256)
__global__ void k_scatconv(const int4* __restrict__ src4,
                           const int4* __restrict__ dst4,
                           const float4* __restrict__ x4,
                           const float4* __restrict__ W4) {
    if (blockIdx.x < SCAT_BLKS) {
        int i = blockIdx.x * blockDim.x + threadIdx.x;
        if (i < NE / 8) {
            int4 sa = src4[2 * i], sb = src4[2 * i + 1];
            int4 da = dst4[2 * i], db = dst4[2 * i + 1];
            int p0 = atomicAdd(&g_cnt[sa.x], 1);
            int p1 = atomicAdd(&g_cnt[sa.y], 1);
            int p2 = atomicAdd(&g_cnt[sa.z], 1);
            int p3 = atomicAdd(&g_cnt[sa.w], 1);
            int p4 = atomicAdd(&g_cnt[sb.x], 1);
            int p5 = atomicAdd(&g_cnt[sb.y], 1);
            int p6 = atomicAdd(&g_cnt[sb.z], 1);
            int p7 = atomicAdd(&g_cnt[sb.w], 1);
            g_slot[sa.x * CAP + p0] = da.x;
            g_slot[sa.y * CAP + p1] = da.y;
            g_slot[sa.z * CAP + p2] = da.z;
            g_slot[sa.w * CAP + p3] = da.w;
            g_slot[sb.x * CAP + p4] = db.x;
            g_slot[sb.y * CAP + p5] = db.y;
            g_slot[sb.z * CAP + p6] = db.z;
            g_slot[sb.w * CAP + p7] = db.w;
        }
    } else {
        int i = (blockIdx.x - SCAT_BLKS) * blockDim.x + threadIdx.x;
        if (i < NN * 16) {
            float4 v0 = x4[i * 2];
            float4 v1 = x4[i * 2 + 1];
            __half2 h0 = __floats2half2_rn(v0.x, v0.y);
            __half2 h1 = __floats2half2_rn(v0.z, v0.w);
            __half2 h2 = __floats2half2_rn(v1.x, v1.y);
            __half2 h3 = __floats2half2_rn(v1.z, v1.w);
            uint4 u;
            u.x = *(unsigned*)&h0; u.y = *(unsigned*)&h1;
            u.z = *(unsigned*)&h2; u.w = *(unsigned*)&h3;
            g_xs4[i] = u;
        } else if (i < NN * 16 + DD * DD / 8) {
            int j = i - NN * 16;
            float4 v0 = W4[j * 2];
            float4 v1 = W4[j * 2 + 1];
            __half2 h0 = __floats2half2_rn(v0.x, v0.y);
            __half2 h1 = __floats2half2_rn(v0.z, v0.w);
            __half2 h2 = __floats2half2_rn(v1.x, v1.y);
            __half2 h3 = __floats2half2_rn(v1.z, v1.w);
            uint4 u;
            u.x = *(unsigned*)&h0; u.y = *(unsigned*)&h1;
            u.z = *(unsigned*)&h2; u.w = *(unsigned*)&h3;
            g_Wh4[j] = u;
        }
    }
}

// ---------------- prep: invdeg (after scat) ----------------------------------
__global__ void k_prep() {
    int i = blockIdx.x * blockDim.x + threadIdx.x;
    if (i < NN) {
        int d = g_cnt[i];
        g_ideg[i] = 1.0f / (float)(d > 1 ? d : 1);
    }
}

// ---------------- gather: warp/node, 16 lanes/edge, fp32 FFMA, 4-edge unroll -
__device__ __forceinline__ void facc(float* a, uint4 p, float w) {
    __half2* hp = (__half2*)&p;
    #pragma unroll
    for (int i = 0; i < 4; i++) {
        float2 f = __half22float2(hp[i]);
        a[2 * i]     = fmaf(f.x, w, a[2 * i]);
        a[2 * i + 1] = fmaf(f.y, w, a[2 * i + 1]);
    }
}

__global__ void k_gather() {
    int gw = (blockIdx.x * blockDim.x + threadIdx.x) >> 5;
    int lane = threadIdx.x & 31;
    if (gw >= NN) return;
    int n = g_cnt[gw];
    const int* slots = &g_slot[gw * CAP];
    int hw = lane >> 4, l16 = lane & 15;
    float a[8] = {0.f, 0.f, 0.f, 0.f, 0.f, 0.f, 0.f, 0.f};
    int e = 0;
    for (; e + 4 <= n; e += 4) {
        int d0 = slots[e + hw];
        int d1 = slots[e + 2 + hw];
        float w0 = g_ideg[d0], w1 = g_ideg[d1];
        uint4 p0 = g_xs4[d0 * 16 + l16];
        uint4 p1 = g_xs4[d1 * 16 + l16];
        facc(a, p0, w0);
        facc(a, p1, w1);
    }
    for (; e < n; e += 2) {
        if (e + hw < n) {
            int d0 = slots[e + hw];
            facc(a, g_xs4[d0 * 16 + l16], g_ideg[d0]);
        }
    }
    #pragma unroll
    for (int i = 0; i < 8; i++)
        a[i] += __shfl_xor_sync(0xffffffffu, a[i], 16);
    if (hw == 0) {
        __half2 h0 = __floats2half2_rn(a[0], a[1]);
        __half2 h1 = __floats2half2_rn(a[2], a[3]);
        __half2 h2 = __floats2half2_rn(a[4], a[5]);
        __half2 h3 = __floats2half2_rn(a[6], a[7]);
        uint4 u;
        u.x = *(unsigned*)&h0; u.y = *(unsigned*)&h1;
        u.z = *(unsigned*)&h2; u.w = *(unsigned*)&h3;
        g_nh4[gw * 16 + l16] = u;
    }
}

// ---------------- mma helpers ------------------------------------------------
__device__ __forceinline__ void ldsm_x4(unsigned* r, const __half* p) {
    unsigned addr = (unsigned)__cvta_generic_to_shared(p);
    asm volatile("ldmatrix.sync.aligned.m8n8.x4.shared.b16 {%0,%1,%2,%3}, [%4];"
                 : "=r"(r[0]), "=r"(r[1]), "=r"(r[2]), "=r"(r[3]) : "r"(addr));
}
__device__ __forceinline__ void mma16816(float* c, const unsigned* a,
                                         unsigned b0, unsigned b1) {
    asm volatile(
        "mma.sync.aligned.m16n8k16.row.col.f32.f16.f16.f32 "
        "{%0,%1,%2,%3}, {%4,%5,%6,%7}, {%8,%9}, {%0,%1,%2,%3};"
        : "+f"(c[0]), "+f"(c[1]), "+f"(c[2]), "+f"(c[3])
        : "r"(a[0]), "r"(a[1]), "r"(a[2]), "r"(a[3]), "r"(b0), "r"(b1));
}

// ---------------- HMMA GEMM + bias + residual + LayerNorm --------------------
// block = 64 rows x 128 cols; warp = 16 rows x 64 cols (acc = 32 regs).
// LN: quad-shuffle partial, cross-warp-pair combine via 1KB smem table.
__global__ void __launch_bounds__(256, 3)
k_gemmln(const float2* __restrict__ x2,
         const float2* __restrict__ bias2,
         const float2* __restrict__ gamma2,
         const float2* __restrict__ beta2,
         float2* __restrict__ out2) {
    extern __shared__ __half sh[];
    __half* sA = sh;                       // [64][LDA]
    __half* sB = sh + MB * LDA;            // [128][LDA]
    float*  sRed = (float*)(sh + (MB + DD) * LDA);  // [64][4]: s0,ss0,s1,ss1
    int t = threadIdx.x, lane = t & 31, warp = t >> 5;
    int wrow = warp >> 1;                  // 0..3
    int wcol = warp & 1;                   // 0..1
    int n0 = blockIdx.x * MB;

    for (int i = t; i < MB * 16; i += 256) {
        int r = i >> 4, c = i & 15;
        uint4 v = (n0 + r < NN) ? g_nh4[(n0 + r) * 16 + c]
                                : make_uint4(0u, 0u, 0u, 0u);
        *(uint4*)&sA[r * LDA + c * 8] = v;
    }
    for (int i = t; i < DD * 16; i += 256) {
        int r = i >> 4, c = i & 15;
        *(uint4*)&sB[r * LDA + c * 8] = g_Wh4[r * 16 + c];
    }
    __syncthreads();

    int mr = wrow * 16;
    int arow = mr + (lane & 15);
    int acol = (lane >> 4) * 8;

    float acc[8][4];
    #pragma unroll
    for (int i = 0; i < 8; i++)
        #pragma unroll
        for (int j = 0; j < 4; j++) acc[i][j] = 0.f;

    int brow_off = (lane & 7) + ((lane >> 4) << 3);
    int bcol = lane & 8;
    #pragma unroll
    for (int kc = 0; kc < 8; kc++) {
        unsigned af[4];
        ldsm_x4(af, &sA[arow * LDA + kc * 16 + acol]);
        #pragma unroll
        for (int p = 0; p < 4; p++) {
            int j0 = wcol * 64 + p * 16;
            unsigned bf[4];
            ldsm_x4(bf, &sB[(j0 + brow_off) * LDA + kc * 16 + bcol]);
            mma16816(acc[2 * p],     af, bf[0], bf[1]);
            mma16816(acc[2 * p + 1], af, bf[2], bf[3]);
        }
    }

    // epilogue: residual + bias; partial LN sums over this warp's 64 cols
    int qrow = lane >> 2;
    int qcol = (lane & 3) * 2;
    int row_lo = n0 + mr + qrow;
    int row_hi = row_lo + 8;
    bool ok_lo = row_lo < NN, ok_hi = row_hi < NN;
    float s_lo = 0.f, ss_lo = 0.f, s_hi = 0.f, ss_hi = 0.f;
    #pragma unroll
    for (int t8 = 0; t8 < 8; t8++) {
        int n = wcol * 64 + (t8 >> 1) * 16 + (t8 & 1) * 8 + qcol;
        float2 bb = bias2[n >> 1];
        float2 xl = ok_lo ? x2[row_lo * 64 + (n >> 1)] : make_float2(0.f, 0.f);
        float2 xh = ok_hi ? x2[row_hi * 64 + (n >> 1)] : make_float2(0.f, 0.f);
        float h0 = acc[t8][0] + xl.x + bb.x;
        float h1 = acc[t8][1] + xl.y + bb.y;
        float h2 = acc[t8][2] + xh.x + bb.x;
        float h3 = acc[t8][3] + xh.y + bb.y;
        acc[t8][0] = h0; acc[t8][1] = h1; acc[t8][2] = h2; acc[t8][3] = h3;
        s_lo += h0 + h1; ss_lo += h0 * h0 + h1 * h1;
        s_hi += h2 + h3; ss_hi += h2 * h2 + h3 * h3;
    }
    #pragma unroll
    for (int o = 1; o <= 2; o <<= 1) {
        s_lo  += __shfl_xor_sync(0xffffffffu, s_lo,  o);
        ss_lo += __shfl_xor_sync(0xffffffffu, ss_lo, o);
        s_hi  += __shfl_xor_sync(0xffffffffu, s_hi,  o);
        ss_hi += __shfl_xor_sync(0xffffffffu, ss_hi, o);
    }
    // cross-warp-pair combine via smem: sRed[row][wcol*2 + {0:s,1:ss}]
    if ((lane & 3) == 0) {
        sRed[(mr + qrow) * 4 + wcol * 2 + 0] = s_lo;
        sRed[(mr + qrow) * 4 + wcol * 2 + 1] = ss_lo;
        sRed[(mr + qrow + 8) * 4 + wcol * 2 + 0] = s_hi;
        sRed[(mr + qrow + 8) * 4 + wcol * 2 + 1] = ss_hi;
    }
    __syncthreads();
    float st_lo = sRed[(mr + qrow) * 4 + 0] + sRed[(mr + qrow) * 4 + 2];
    float sst_lo = sRed[(mr + qrow) * 4 + 1] + sRed[(mr + qrow) * 4 + 3];
    float st_hi = sRed[(mr + qrow + 8) * 4 + 0] + sRed[(mr + qrow + 8) * 4 + 2];
    float sst_hi = sRed[(mr + qrow + 8) * 4 + 1] + sRed[(mr + qrow + 8) * 4 + 3];

    float m_lo = st_lo * (1.0f / 128.0f);
    float v_lo = sst_lo * (1.0f / 128.0f) - m_lo * m_lo;
    float r_lo = rsqrtf(v_lo + LN_EPS);
    float m_hi = st_hi * (1.0f / 128.0f);
    float v_hi = sst_hi * (1.0f / 128.0f) - m_hi * m_hi;
    float r_hi = rsqrtf(v_hi + LN_EPS);

    #pragma unroll
    for (int t8 = 0; t8 < 8; t8++) {
        int n = wcol * 64 + (t8 >> 1) * 16 + (t8 & 1) * 8 + qcol;
        float2 gg = gamma2[n >> 1];
        float2 tt = beta2[n >> 1];
        if (ok_lo) {
            float2 o;
            o.x = (acc[t8][0] - m_lo) * r_lo * gg.x + tt.x;
            o.y = (acc[t8][1] - m_lo) * r_lo * gg.y + tt.y;
            out2[row_lo * 64 + (n >> 1)] = o;
        }
        if (ok_hi) {
            float2 o;
            o.x = (acc[t8][2] - m_hi) * r_hi * gg.x + tt.x;
            o.y = (acc[t8][3] - m_hi) * r_hi * gg.y + tt.y;
            out2[row_hi * 64 + (n >> 1)] = o;
        }
    }
}

// ---------------- launch -----------------------------------------------------
extern "C" void kernel_launch(void* const* d_in, const int* in_sizes, int n_in,
                              void* d_out, int out_size) {
    const float* x     = (const float*)d_in[0];
    const float* W     = (const float*)d_in[1];
    const float* bias  = (const float*)d_in[2];
    const float* gamma = (const float*)d_in[3];
    const float* beta  = (const float*)d_in[4];
    const int*   ei    = (const int*)d_in[5];
    const int4*  src4  = (const int4*)ei;
    const int4*  dst4  = (const int4*)(ei + NE);

    const int smem = (MB + DD) * LDA * (int)sizeof(__half) + MB * 4 * (int)sizeof(float);
    cudaFuncSetAttribute(k_gemmln, cudaFuncAttributeMaxDynamicSharedMemorySize, smem);

    void* cnt_ptr = nullptr;
    cudaGetSymbolAddress(&cnt_ptr, g_cnt);
    cudaMemsetAsync(cnt_ptr, 0, NN * sizeof(int));

    const int conv_blks = (NN * 16 + DD * DD / 8 + 255) / 256;
    k_scatconv<<<SCAT_BLKS + conv_blks, 256>>>(src4, dst4,
                                               (const float4*)x,
                                               (const float4*)W);
    k_prep<<<(NN + 255) / 256, 256>>>();
    k_gather<<<(NN * 32 + 255) / 256, 256>>>();
    k_gemmln<<<(NN + MB - 1) / MB, 256, smem>>>(
        (const float2*)x, (const float2*)bias, (const float2*)gamma,
        (const float2*)beta, (float2*)d_out);
}